// round 9
// baseline (speedup 1.0000x reference)
#include <cuda_runtime.h>

#define BN 128
#define TN 512
#define HN 256
#define G4N 1024
typedef unsigned long long ULL;

__device__ __forceinline__ ULL pack2(float x, float y){ULL r;asm("mov.b64 %0,{%1,%2};":"=l"(r):"f"(x),"f"(y));return r;}
__device__ __forceinline__ void unpack2(ULL v,float&x,float&y){asm("mov.b64 {%0,%1},%2;":"=f"(x),"=f"(y):"l"(v));}
__device__ __forceinline__ ULL fma2(ULL a,ULL b,ULL c){ULL d;asm("fma.rn.f32x2 %0,%1,%2,%3;":"=l"(d):"l"(a),"l"(b),"l"(c));return d;}

// scratch (static __device__: no allocation allowed)
__device__ __align__(16) float g_h0[TN*BN*512];        // layer0 out [t][b][2H]
__device__ __align__(16) float g_gx1[2u*TN*BN*G4N];    // layer1 gate inputs [dir][t][b][4H]
__device__ __align__(16) float g_hstate[2*BN*HN];      // per-dir h
__device__ __align__(16) float g_pool[BN*512];         // mean_t h1 [b][2H]
__device__ unsigned g_bar_count[2];
__device__ unsigned g_bar_gen[2];

__device__ __forceinline__ float fast_tanh(float x){
    float ax=fabsf(x), e=__expf(-2.0f*ax), r=(1.0f-e)/(1.0f+e);
    return (x>=0.0f)?r:-r;
}
__device__ __forceinline__ float fast_sigmoid(float x){ return 0.5f*fast_tanh(0.5f*x)+0.5f; }

// dynamic smem layout (bytes)
#define SM_W    0                    // float [256][64]  wh^T slice   65536
#define SM_H2   65536                // ULL   [32][257]  dup h        65792
#define SM_G    (SM_H2+32*257*8)     // float [64][33]   gate staging  8448
#define SM_BS   (SM_G+64*33*4)       // float [64]
#define SM_WI0  (SM_BS+64*4)         // float [64][4]
#define SM_X    (SM_WI0+64*4*4)      // float [32][4]
#define SM_TOT  (SM_X+32*4*4)

template<int LAYER>
__global__ void __launch_bounds__(256,1) lstm_scan_kernel(
    const float* __restrict__ x, const float* __restrict__ w_ih0,
    const float* __restrict__ w_hh, const float* __restrict__ b_ih,
    const float* __restrict__ b_hh)
{
    extern __shared__ char smem[];
    float* w_s    = (float*)(smem+SM_W);
    ULL*   h2_s   = (ULL*)  (smem+SM_H2);
    float* G_s    = (float*)(smem+SM_G);
    float* bsum_s = (float*)(smem+SM_BS);
    float* wi0_s  = (float*)(smem+SM_WI0);
    float* x_s    = (float*)(smem+SM_X);

    const int bx=blockIdx.x, dir=bx>>6, cc=bx&63;
    const int btile=cc>>4, ntile=cc&15, tx=threadIdx.x;

    // stage recurrent weights transposed: w_s[k][jl], jl = gate*16 + nn (one-time)
    for(int i=tx;i<64*256;i+=256){
        int jl=i>>8, k=i&255, gate=jl>>4, nn=jl&15;
        int row=gate*256+ntile*16+nn;
        w_s[k*64+jl]=w_hh[(dir*G4N+row)*HN+k];
    }
    for(int jl=tx;jl<64;jl+=256){
        int gate=jl>>4, nn=jl&15, row=gate*256+ntile*16+nn;
        bsum_s[jl]=b_ih[dir*G4N+row]+b_hh[dir*G4N+row];
        if(LAYER==0){
            #pragma unroll
            for(int d=0;d<4;d++) wi0_s[jl*4+d]=w_ih0[(dir*G4N+row)*4+d];
        }
    }

    const int jgroup=tx&15, bgroup=tx>>4;
    const int j0=jgroup*4, b0=bgroup*2, bglob0=btile*32;
    float c0=0.f,c1=0.f,s0=0.f,s1=0.f;

    unsigned bar_base=0;
    if(tx==0) bar_base=*(volatile unsigned*)&g_bar_gen[dir];
    __syncthreads();

    for(int s=0;s<TN;s++){
        const int t = dir ? (TN-1-s) : s;

        if(LAYER==0 && tx<128){
            int bb=tx>>2, d=tx&3;
            x_s[tx]=x[((bglob0+bb)*TN+t)*4+d];
        }
        if(s>0){
            for(int i=tx;i<32*256;i+=256){               // reload full h tile, dup-packed
                int bb=i>>8, k=i&255;
                float v=__ldcg(&g_hstate[(dir*BN+bglob0+bb)*HN+k]);
                h2_s[bb*257+k]=pack2(v,v);
            }
        }
        __syncthreads();

        // gate pre-activation base
        float base[2][4];
        if(LAYER==0){
            #pragma unroll
            for(int bi=0;bi<2;bi++){
                float x0=x_s[(b0+bi)*4+0], x1=x_s[(b0+bi)*4+1];
                float x2=x_s[(b0+bi)*4+2], x3=x_s[(b0+bi)*4+3];
                #pragma unroll
                for(int jj=0;jj<4;jj++){
                    int jl=j0+jj;
                    base[bi][jj]=bsum_s[jl]+wi0_s[jl*4+0]*x0+wi0_s[jl*4+1]*x1
                                           +wi0_s[jl*4+2]*x2+wi0_s[jl*4+3]*x3;
                }
            }
        } else {
            const int gate=j0>>4, nn0=j0&15;
            const long gb=((long)(dir*TN+t)*BN)*G4N;
            #pragma unroll
            for(int bi=0;bi<2;bi++){
                float4 gv=*(const float4*)&g_gx1[gb+(long)(bglob0+b0+bi)*G4N+gate*256+ntile*16+nn0];
                base[bi][0]=gv.x+bsum_s[j0+0]; base[bi][1]=gv.y+bsum_s[j0+1];
                base[bi][2]=gv.z+bsum_s[j0+2]; base[bi][3]=gv.w+bsum_s[j0+3];
            }
        }
        ULL acc00=pack2(base[0][0],base[0][1]), acc01=pack2(base[0][2],base[0][3]);
        ULL acc10=pack2(base[1][0],base[1][1]), acc11=pack2(base[1][2],base[1][3]);

        // recurrent GEMM: g += h @ wh^T  (f32x2)
        if(s>0){
            const ULL* wp=(const ULL*)w_s+(j0>>1);
            const ULL* hA=h2_s+b0*257;
            const ULL* hB=h2_s+(b0+1)*257;
            #pragma unroll 4
            for(int k=0;k<256;k++){
                ULL ha=hA[k], hb=hB[k];
                ulonglong2 ww=*(const ulonglong2*)(wp+k*32);
                acc00=fma2(ww.x,ha,acc00); acc01=fma2(ww.y,ha,acc01);
                acc10=fma2(ww.x,hb,acc10); acc11=fma2(ww.y,hb,acc11);
            }
        }

        // stage gates for state-update transpose
        {
            float f0,f1;
            unpack2(acc00,f0,f1); G_s[(j0+0)*33+b0]  =f0; G_s[(j0+1)*33+b0]  =f1;
            unpack2(acc01,f0,f1); G_s[(j0+2)*33+b0]  =f0; G_s[(j0+3)*33+b0]  =f1;
            unpack2(acc10,f0,f1); G_s[(j0+0)*33+b0+1]=f0; G_s[(j0+1)*33+b0+1]=f1;
            unpack2(acc11,f0,f1); G_s[(j0+2)*33+b0+1]=f0; G_s[(j0+3)*33+b0+1]=f1;
        }
        __syncthreads();

        // LSTM cell update: thread owns (b0,b0+1) x n
        {
            const int nn=jgroup, n=ntile*16+nn;
            #pragma unroll
            for(int bi=0;bi<2;bi++){
                float gi=G_s[(0*16+nn)*33+b0+bi];
                float gf=G_s[(1*16+nn)*33+b0+bi];
                float gg=G_s[(2*16+nn)*33+b0+bi];
                float go=G_s[(3*16+nn)*33+b0+bi];
                float c = bi?c1:c0;
                c = fast_sigmoid(gf)*c + fast_sigmoid(gi)*fast_tanh(gg);
                float h = fast_sigmoid(go)*fast_tanh(c);
                if(bi) c1=c; else c0=c;
                int bg=bglob0+b0+bi;
                __stcg(&g_hstate[(dir*BN+bg)*HN+n], h);
                if(LAYER==0) g_h0[((t*BN)+bg)*512+dir*256+n]=h;
                else { if(bi) s1+=h; else s0+=h; }
            }
        }

        // per-direction grid barrier between steps
        if(s+1<TN){
            __syncthreads();
            if(tx==0){
                __threadfence();
                unsigned old=atomicAdd(&g_bar_count[dir],1u);
                if(old==63u){
                    g_bar_count[dir]=0u;
                    __threadfence();
                    atomicAdd(&g_bar_gen[dir],1u);
                } else {
                    unsigned target=bar_base+(unsigned)(s+1);
                    while(*(volatile unsigned*)&g_bar_gen[dir]<target){}
                    __threadfence();
                }
            }
            __syncthreads();
        }
    }

    if(LAYER==1){
        const float inv=1.0f/(float)TN;
        const int n=ntile*16+jgroup;
        g_pool[(bglob0+b0  )*512+dir*256+n]=s0*inv;
        g_pool[(bglob0+b0+1)*512+dir*256+n]=s1*inv;
    }
}

// gx1 = h0cat @ w_ih1^T (no bias). M=65536 (t,b), N=1024, K=512.
// CTA 128m x 64j, thread 4m x 8j, f32x2. grid.x = jt(16)+16*dir, grid.y = mtile.
__global__ void __launch_bounds__(256,2) gx1_gemm_kernel(const float* __restrict__ w_ih1)
{
    __shared__ __align__(16) float A_s[128*33];   // [m][k], pad 1
    __shared__ __align__(16) float B_s[32*66];    // [k][j], stride 66

    const int dir=blockIdx.x>>4, jt=blockIdx.x&15, mt=blockIdx.y, tx=threadIdx.x;
    const int jgrp=tx&7, mgrp=tx>>3;
    const int j0=jgrp*8, m0=mgrp*4;
    const int mbase=mt*128, jbase=jt*64;

    ULL acc[4][4];
    #pragma unroll
    for(int i=0;i<4;i++)
        #pragma unroll
        for(int j=0;j<4;j++) acc[i][j]=0ull;

    for(int kc=0;kc<512;kc+=32){
        for(int i=tx;i<4096;i+=256){                  // A: 128m x 32k
            int mm=i>>5, kk=i&31;
            A_s[mm*33+kk]=g_h0[(mbase+mm)*512+kc+kk];
        }
        for(int i=tx;i<2048;i+=256){                  // B: 64j x 32k
            int jj=i>>5, kk=i&31;
            B_s[kk*66+jj]=w_ih1[((dir*G4N)+jbase+jj)*512+kc+kk];
        }
        __syncthreads();
        #pragma unroll
        for(int k=0;k<32;k++){
            float a0=A_s[(m0+0)*33+k], a1=A_s[(m0+1)*33+k];
            float a2=A_s[(m0+2)*33+k], a3=A_s[(m0+3)*33+k];
            ULL d0=pack2(a0,a0), d1=pack2(a1,a1), d2=pack2(a2,a2), d3=pack2(a3,a3);
            const ULL* br=(const ULL*)(B_s+k*66)+jgrp*4;
            ULL b0v=br[0], b1v=br[1], b2v=br[2], b3v=br[3];
            acc[0][0]=fma2(b0v,d0,acc[0][0]); acc[0][1]=fma2(b1v,d0,acc[0][1]);
            acc[0][2]=fma2(b2v,d0,acc[0][2]); acc[0][3]=fma2(b3v,d0,acc[0][3]);
            acc[1][0]=fma2(b0v,d1,acc[1][0]); acc[1][1]=fma2(b1v,d1,acc[1][1]);
            acc[1][2]=fma2(b2v,d1,acc[1][2]); acc[1][3]=fma2(b3v,d1,acc[1][3]);
            acc[2][0]=fma2(b0v,d2,acc[2][0]); acc[2][1]=fma2(b1v,d2,acc[2][1]);
            acc[2][2]=fma2(b2v,d2,acc[2][2]); acc[2][3]=fma2(b3v,d2,acc[2][3]);
            acc[3][0]=fma2(b0v,d3,acc[3][0]); acc[3][1]=fma2(b1v,d3,acc[3][1]);
            acc[3][2]=fma2(b2v,d3,acc[3][2]); acc[3][3]=fma2(b3v,d3,acc[3][3]);
        }
        __syncthreads();
    }

    #pragma unroll
    for(int i=0;i<4;i++){
        int m=mbase+m0+i, t=m>>7, b=m&127;
        float2* dst=(float2*)&g_gx1[(((long)dir*TN+t)*BN+b)*G4N+jbase+j0];
        #pragma unroll
        for(int j=0;j<4;j++){
            float lo,hi; unpack2(acc[i][j],lo,hi);
            dst[j]=make_float2(lo,hi);
        }
    }
}

__global__ void fc_kernel(const float* __restrict__ fc_w, const float* __restrict__ fc_b,
                          float* __restrict__ out)
{
    int b=threadIdx.x>>1, o=threadIdx.x&1;
    float s=fc_b[o];
    const float* p=&g_pool[b*512];
    const float* w=&fc_w[o*512];
    #pragma unroll 8
    for(int k=0;k<512;k++) s+=p[k]*w[k];
    out[b*2+o]=s;
}

extern "C" void kernel_launch(void* const* d_in, const int* in_sizes, int n_in,
                              void* d_out, int out_size)
{
    const float* x     =(const float*)d_in[0];
    const float* w_ih0 =(const float*)d_in[1];
    const float* w_hh0 =(const float*)d_in[2];
    const float* b_ih0 =(const float*)d_in[3];
    const float* b_hh0 =(const float*)d_in[4];
    const float* w_ih1 =(const float*)d_in[5];
    const float* w_hh1 =(const float*)d_in[6];
    const float* b_ih1 =(const float*)d_in[7];
    const float* b_hh1 =(const float*)d_in[8];
    const float* fc_w  =(const float*)d_in[9];
    const float* fc_b  =(const float*)d_in[10];
    float* out=(float*)d_out;

    cudaFuncSetAttribute(lstm_scan_kernel<0>, cudaFuncAttributeMaxDynamicSharedMemorySize, SM_TOT);
    cudaFuncSetAttribute(lstm_scan_kernel<1>, cudaFuncAttributeMaxDynamicSharedMemorySize, SM_TOT);

    lstm_scan_kernel<0><<<128,256,SM_TOT>>>(x, w_ih0, w_hh0, b_ih0, b_hh0);
    gx1_gemm_kernel<<<dim3(32,512),256>>>(w_ih1);
    lstm_scan_kernel<1><<<128,256,SM_TOT>>>(nullptr, nullptr, w_hh1, b_ih1, b_hh1);
    fc_kernel<<<1,256>>>(fc_w, fc_b, out);
}

// round 11
// speedup vs baseline: 1.0625x; 1.0625x over previous
#include <cuda_runtime.h>

#define BN 128
#define TN 512
#define HN 256
#define G4N 1024
typedef unsigned long long ULL;

__device__ __forceinline__ ULL pack2(float x, float y){ULL r;asm("mov.b64 %0,{%1,%2};":"=l"(r):"f"(x),"f"(y));return r;}
__device__ __forceinline__ void unpack2(ULL v,float&x,float&y){asm("mov.b64 {%0,%1},%2;":"=f"(x),"=f"(y):"l"(v));}
__device__ __forceinline__ ULL fma2(ULL a,ULL b,ULL c){ULL d;asm("fma.rn.f32x2 %0,%1,%2,%3;":"=l"(d):"l"(a),"l"(b),"l"(c));return d;}
__device__ __forceinline__ unsigned smem_u32(const void* p){ return (unsigned)__cvta_generic_to_shared(p); }
__device__ __forceinline__ void cp16(unsigned dst, const void* src){
    asm volatile("cp.async.cg.shared.global [%0], [%1], 16;\n" :: "r"(dst), "l"(src) : "memory");
}
__device__ __forceinline__ void cp_commit(){ asm volatile("cp.async.commit_group;\n":::"memory"); }
__device__ __forceinline__ void cp_wait0(){ asm volatile("cp.async.wait_group 0;\n":::"memory"); }

// ---- scratch (static __device__: no allocation allowed) ----
__device__ __align__(16) float g_h0[TN*BN*512];          // layer0 out [t][b][2H]
__device__ __align__(16) float g_gx1[2u*TN*BN*G4N];      // layer1 gate inputs [dir][t][b][4H]
__device__ __align__(16) ULL   g_h2state[2*HN*BN];       // dup-packed h, [dir][k][b]
__device__ __align__(16) float g_pool[BN*512];           // mean_t h1 [b][2H]
__device__ unsigned g_cnt2[8][2];
__device__ unsigned g_flag2[8][2];
__device__ unsigned g_done2[8];

__device__ __forceinline__ float fast_tanh(float x){
    float ax=fabsf(x), e=__expf(-2.0f*ax), r=(1.0f-e)/(1.0f+e);
    return (x>=0.0f)?r:-r;
}
__device__ __forceinline__ float fast_sigmoid(float x){ return 0.5f*fast_tanh(0.5f*x)+0.5f; }

// ---- dynamic smem layout (bytes) ----
#define SM_W    0                      // float [256][64]  wh^T slice    65536
#define SM_H2   65536                  // ULL   [256][34]  dup h (k-major) 69632
#define SM_G    (SM_H2+256*34*8)       // float [64][33]   gate staging   8448
#define SM_BS   (SM_G+64*33*4)         // float [64]
#define SM_WI0  (SM_BS+64*4)           // float [64][4]
#define SM_TOT  (SM_WI0+64*4*4)        // 144896

template<int LAYER>
__global__ void __launch_bounds__(256,1) lstm_scan_kernel(
    const float* __restrict__ x, const float* __restrict__ w_ih0,
    const float* __restrict__ w_hh, const float* __restrict__ b_ih,
    const float* __restrict__ b_hh)
{
    extern __shared__ char smem[];
    float* w_s    = (float*)(smem+SM_W);
    ULL*   h2_s   = (ULL*)  (smem+SM_H2);
    float* G_s    = (float*)(smem+SM_G);
    float* bsum_s = (float*)(smem+SM_BS);
    float* wi0_s  = (float*)(smem+SM_WI0);
    const unsigned h2_base = smem_u32(h2_s);

    const int bx=blockIdx.x, dir=bx>>6, cc=bx&63;
    const int btile=cc>>4, ntile=cc&15, tx=threadIdx.x;
    const int grp = dir*4 + btile;           // 16-CTA barrier group (shared batch rows)

    // one-time weight staging: w_s[k][jl], jl = gate*16 + nn
    for(int i=tx;i<64*256;i+=256){
        int jl=i>>8, k=i&255, gate=jl>>4, nn=jl&15;
        int row=gate*256+ntile*16+nn;
        w_s[k*64+jl]=w_hh[(dir*G4N+row)*HN+k];
    }
    for(int jl=tx;jl<64;jl+=256){
        int gate=jl>>4, nn=jl&15, row=gate*256+ntile*16+nn;
        bsum_s[jl]=b_ih[dir*G4N+row]+b_hh[dir*G4N+row];
        if(LAYER==0){
            #pragma unroll
            for(int d=0;d<4;d++) wi0_s[jl*4+d]=w_ih0[(dir*G4N+row)*4+d];
        }
    }

    // lane mapping: warp spans 4 j-groups x 8 b-groups (cuts crossbar traffic)
    const int wq=tx>>5;
    const int jgroup=(wq&3)*4 + (tx&3);
    const int bgroup=(wq>>2)*8 + ((tx>>2)&7);
    const int j0=jgroup*4, b0=bgroup*2, bglob0=btile*32;
    float c0=0.f,c1=0.f,s0=0.f,s1=0.f;

    float4 pf0, pf1, npf0, npf1;
    // prefetch gate-input base for the first step
    {
        int t0 = dir ? TN-1 : 0;
        if(LAYER==0){
            npf0 = *(const float4*)&x[((bglob0+b0  )*TN + t0)*4];
            npf1 = *(const float4*)&x[((bglob0+b0+1)*TN + t0)*4];
        } else {
            const long gb=((long)(dir*TN+t0)*BN)*G4N;
            const int col=(j0>>4)*256+ntile*16+(j0&15);
            npf0 = *(const float4*)&g_gx1[gb + (long)(bglob0+b0  )*G4N + col];
            npf1 = *(const float4*)&g_gx1[gb + (long)(bglob0+b0+1)*G4N + col];
        }
    }
    pf0=npf0; pf1=npf1;
    __syncthreads();   // weights staged

    for(int s=0;s<TN;s++){
        const int t = dir ? (TN-1-s) : s;

        cp_wait0();          // h tile (issued at end of prev step) in smem
        __syncthreads();

        // gate pre-activation base (from prefetched regs)
        float base[2][4];
        if(LAYER==0){
            #pragma unroll
            for(int bi=0;bi<2;bi++){
                float4 xv = bi ? pf1 : pf0;
                #pragma unroll
                for(int jj=0;jj<4;jj++){
                    int jl=j0+jj;
                    base[bi][jj]=bsum_s[jl]+wi0_s[jl*4+0]*xv.x+wi0_s[jl*4+1]*xv.y
                                           +wi0_s[jl*4+2]*xv.z+wi0_s[jl*4+3]*xv.w;
                }
            }
        } else {
            #pragma unroll
            for(int bi=0;bi<2;bi++){
                float4 gv = bi ? pf1 : pf0;
                base[bi][0]=gv.x+bsum_s[j0+0]; base[bi][1]=gv.y+bsum_s[j0+1];
                base[bi][2]=gv.z+bsum_s[j0+2]; base[bi][3]=gv.w+bsum_s[j0+3];
            }
        }
        ULL acc00=pack2(base[0][0],base[0][1]), acc01=pack2(base[0][2],base[0][3]);
        ULL acc10=pack2(base[1][0],base[1][1]), acc11=pack2(base[1][2],base[1][3]);

        // prefetch next step's gate inputs (independent of h; overlaps GEMM)
        if(s+1<TN){
            int tn = dir ? (t-1) : (t+1);
            if(LAYER==0){
                npf0 = *(const float4*)&x[((bglob0+b0  )*TN + tn)*4];
                npf1 = *(const float4*)&x[((bglob0+b0+1)*TN + tn)*4];
            } else {
                const long gb=((long)(dir*TN+tn)*BN)*G4N;
                const int col=(j0>>4)*256+ntile*16+(j0&15);
                npf0 = *(const float4*)&g_gx1[gb + (long)(bglob0+b0  )*G4N + col];
                npf1 = *(const float4*)&g_gx1[gb + (long)(bglob0+b0+1)*G4N + col];
            }
        }

        // recurrent GEMM: g += h @ wh^T  (f32x2; 2xLDS.128 + 4xFFMA2 per k)
        if(s>0){
            const ULL* wp=(const ULL*)w_s + (j0>>1);
            const ULL* hp=h2_s + b0;
            #pragma unroll 8
            for(int k=0;k<256;k++){
                ulonglong2 hh=*(const ulonglong2*)(hp + k*34);
                ulonglong2 ww=*(const ulonglong2*)(wp + k*32);
                acc00=fma2(ww.x,hh.x,acc00); acc01=fma2(ww.y,hh.x,acc01);
                acc10=fma2(ww.x,hh.y,acc10); acc11=fma2(ww.y,hh.y,acc11);
            }
        }

        // stage gates for state-update transpose
        {
            float f0,f1;
            unpack2(acc00,f0,f1); G_s[(j0+0)*33+b0]  =f0; G_s[(j0+1)*33+b0]  =f1;
            unpack2(acc01,f0,f1); G_s[(j0+2)*33+b0]  =f0; G_s[(j0+3)*33+b0]  =f1;
            unpack2(acc10,f0,f1); G_s[(j0+0)*33+b0+1]=f0; G_s[(j0+1)*33+b0+1]=f1;
            unpack2(acc11,f0,f1); G_s[(j0+2)*33+b0+1]=f0; G_s[(j0+3)*33+b0+1]=f1;
        }
        __syncthreads();

        // LSTM cell update: thread owns (b0,b0+1) x n
        {
            const int nn=jgroup, n=ntile*16+nn;
            #pragma unroll
            for(int bi=0;bi<2;bi++){
                float gi=G_s[(0*16+nn)*33+b0+bi];
                float gf=G_s[(1*16+nn)*33+b0+bi];
                float gg=G_s[(2*16+nn)*33+b0+bi];
                float go=G_s[(3*16+nn)*33+b0+bi];
                float c = bi?c1:c0;
                c = fast_sigmoid(gf)*c + fast_sigmoid(gi)*fast_tanh(gg);
                float h = fast_sigmoid(go)*fast_tanh(c);
                if(bi) c1=c; else c0=c;
                int bg=bglob0+b0+bi;
                __stcg(&g_h2state[(dir*HN+n)*BN+bg], pack2(h,h));
                if(LAYER==0) g_h0[((t*BN)+bg)*512+dir*256+n]=h;
                else { if(bi) s1+=h; else s0+=h; }
            }
        }
        pf0=npf0; pf1=npf1;

        // inter-step barrier over the 16 CTAs sharing (dir,btile)
        if(s+1<TN){
            __syncthreads();
            if(tx==0){
                const int p=s&1; const unsigned target=(unsigned)(s+1);
                __threadfence();
                unsigned old=atomicAdd(&g_cnt2[grp][p],1u);
                if(old==15u){
                    g_cnt2[grp][p]=0u;
                    __threadfence();
                    atomicExch(&g_flag2[grp][p], target);
                } else {
                    while((int)(__ldcg(&g_flag2[grp][p]) - target) < 0) __nanosleep(32);
                    __threadfence();
                }
            }
            __syncthreads();
            // async-copy next h tile: [k=0..255][32 b] dup-packed, 16B chunks
            {
                const ULL* src_base=&g_h2state[(dir*HN)*BN + bglob0];
                for(int i=tx;i<4096;i+=256){
                    int kk=i>>4, c2=(i&15)*2;
                    cp16(h2_base + (unsigned)((kk*34+c2)*8), src_base + kk*BN + c2);
                }
                cp_commit();
            }
        }
    }

    // self-clean barrier state for the next launch
    if(tx==0){
        unsigned old=atomicAdd(&g_done2[grp],1u);
        if(old==15u){
            g_done2[grp]=0u; g_flag2[grp][0]=0u; g_flag2[grp][1]=0u;
            __threadfence();
        }
    }

    if(LAYER==1){
        const float inv=1.0f/(float)TN;
        const int n=ntile*16+jgroup;
        g_pool[(bglob0+b0  )*512+dir*256+n]=s0*inv;
        g_pool[(bglob0+b0+1)*512+dir*256+n]=s1*inv;
    }
}

// gx1 = h0cat @ w_ih1^T (no bias). M=65536 (t,b), N=1024 per dir, K=512.
__global__ void __launch_bounds__(256,2) gx1_gemm_kernel(const float* __restrict__ w_ih1)
{
    __shared__ __align__(16) float A_s[128*33];
    __shared__ __align__(16) float B_s[32*66];

    const int dir=blockIdx.x>>4, jt=blockIdx.x&15, mt=blockIdx.y, tx=threadIdx.x;
    const int jgrp=tx&7, mgrp=tx>>3;
    const int j0=jgrp*8, m0=mgrp*4;
    const int mbase=mt*128, jbase=jt*64;

    ULL acc[4][4];
    #pragma unroll
    for(int i=0;i<4;i++)
        #pragma unroll
        for(int j=0;j<4;j++) acc[i][j]=0ull;

    for(int kc=0;kc<512;kc+=32){
        for(int i=tx;i<4096;i+=256){
            int mm=i>>5, kk=i&31;
            A_s[mm*33+kk]=g_h0[(mbase+mm)*512+kc+kk];
        }
        for(int i=tx;i<2048;i+=256){
            int jj=i>>5, kk=i&31;
            B_s[kk*66+jj]=w_ih1[((dir*G4N)+jbase+jj)*512+kc+kk];
        }
        __syncthreads();
        #pragma unroll
        for(int k=0;k<32;k++){
            float a0=A_s[(m0+0)*33+k], a1=A_s[(m0+1)*33+k];
            float a2=A_s[(m0+2)*33+k], a3=A_s[(m0+3)*33+k];
            ULL d0=pack2(a0,a0), d1=pack2(a1,a1), d2=pack2(a2,a2), d3=pack2(a3,a3);
            const ULL* br=(const ULL*)(B_s+k*66)+jgrp*4;
            ULL b0v=br[0], b1v=br[1], b2v=br[2], b3v=br[3];
            acc[0][0]=fma2(b0v,d0,acc[0][0]); acc[0][1]=fma2(b1v,d0,acc[0][1]);
            acc[0][2]=fma2(b2v,d0,acc[0][2]); acc[0][3]=fma2(b3v,d0,acc[0][3]);
            acc[1][0]=fma2(b0v,d1,acc[1][0]); acc[1][1]=fma2(b1v,d1,acc[1][1]);
            acc[1][2]=fma2(b2v,d1,acc[1][2]); acc[1][3]=fma2(b3v,d1,acc[1][3]);
            acc[2][0]=fma2(b0v,d2,acc[2][0]); acc[2][1]=fma2(b1v,d2,acc[2][1]);
            acc[2][2]=fma2(b2v,d2,acc[2][2]); acc[2][3]=fma2(b3v,d2,acc[2][3]);
            acc[3][0]=fma2(b0v,d3,acc[3][0]); acc[3][1]=fma2(b1v,d3,acc[3][1]);
            acc[3][2]=fma2(b2v,d3,acc[3][2]); acc[3][3]=fma2(b3v,d3,acc[3][3]);
        }
        __syncthreads();
    }

    #pragma unroll
    for(int i=0;i<4;i++){
        int m=mbase+m0+i, t=m>>7, b=m&127;
        float2* dst=(float2*)&g_gx1[(((long)dir*TN+t)*BN+b)*G4N+jbase+j0];
        #pragma unroll
        for(int j=0;j<4;j++){
            float lo,hi; unpack2(acc[i][j],lo,hi);
            dst[j]=make_float2(lo,hi);
        }
    }
}

__global__ void fc_kernel(const float* __restrict__ fc_w, const float* __restrict__ fc_b,
                          float* __restrict__ out)
{
    int b=blockIdx.x;
    int o=threadIdx.x>>5, lane=threadIdx.x&31;
    const float* p=&g_pool[b*512];
    const float* w=&fc_w[o*512];
    float s=0.f;
    #pragma unroll 4
    for(int k=lane;k<512;k+=32) s+=p[k]*w[k];
    #pragma unroll
    for(int off=16;off;off>>=1) s+=__shfl_xor_sync(0xffffffffu,s,off);
    if(lane==0) out[b*2+o]=s+fc_b[o];
}

extern "C" void kernel_launch(void* const* d_in, const int* in_sizes, int n_in,
                              void* d_out, int out_size)
{
    const float* x     =(const float*)d_in[0];
    const float* w_ih0 =(const float*)d_in[1];
    const float* w_hh0 =(const float*)d_in[2];
    const float* b_ih0 =(const float*)d_in[3];
    const float* b_hh0 =(const float*)d_in[4];
    const float* w_ih1 =(const float*)d_in[5];
    const float* w_hh1 =(const float*)d_in[6];
    const float* b_ih1 =(const float*)d_in[7];
    const float* b_hh1 =(const float*)d_in[8];
    const float* fc_w  =(const float*)d_in[9];
    const float* fc_b  =(const float*)d_in[10];
    float* out=(float*)d_out;

    cudaFuncSetAttribute(lstm_scan_kernel<0>, cudaFuncAttributeMaxDynamicSharedMemorySize, SM_TOT);
    cudaFuncSetAttribute(lstm_scan_kernel<1>, cudaFuncAttributeMaxDynamicSharedMemorySize, SM_TOT);

    lstm_scan_kernel<0><<<128,256,SM_TOT>>>(x, w_ih0, w_hh0, b_ih0, b_hh0);
    gx1_gemm_kernel<<<dim3(32,512),256>>>(w_ih1);
    lstm_scan_kernel<1><<<128,256,SM_TOT>>>(nullptr, nullptr, w_hh1, b_ih1, b_hh1);
    fc_kernel<<<128,64>>>(fc_w, fc_b, out);
}

// round 14
// speedup vs baseline: 1.3183x; 1.2408x over previous
#include <cuda_runtime.h>

#define BN 128
#define TN 512
#define HN 256
#define G4N 1024
typedef unsigned long long ULL;

__device__ __forceinline__ ULL pack2(float x, float y){ULL r;asm("mov.b64 %0,{%1,%2};":"=l"(r):"f"(x),"f"(y));return r;}
__device__ __forceinline__ void unpack2(ULL v,float&x,float&y){asm("mov.b64 {%0,%1},%2;":"=f"(x),"=f"(y):"l"(v));}
__device__ __forceinline__ ULL fma2(ULL a,ULL b,ULL c){ULL d;asm("fma.rn.f32x2 %0,%1,%2,%3;":"=l"(d):"l"(a),"l"(b),"l"(c));return d;}
__device__ __forceinline__ unsigned smem_u32(const void* p){ return (unsigned)__cvta_generic_to_shared(p); }
__device__ __forceinline__ void cp16(unsigned dst, const void* src){
    asm volatile("cp.async.cg.shared.global [%0], [%1], 16;\n" :: "r"(dst), "l"(src) : "memory");
}
__device__ __forceinline__ void cp_commit(){ asm volatile("cp.async.commit_group;\n":::"memory"); }
__device__ __forceinline__ void cp_wait0(){ asm volatile("cp.async.wait_group 0;\n":::"memory"); }
__device__ __forceinline__ void cp_wait1(){ asm volatile("cp.async.wait_group 1;\n":::"memory"); }

__device__ __forceinline__ float tanh_ap(float x){float y;asm("tanh.approx.f32 %0,%1;":"=f"(y):"f"(x));return y;}
__device__ __forceinline__ float sig_ap(float x){ return fmaf(tanh_ap(0.5f*x),0.5f,0.5f); }

// ---- scratch (static __device__: no allocation allowed) ----
__device__ __align__(16) float g_h0[TN*BN*512];          // layer0 out [t][b][2H]
__device__ __align__(16) float g_gx1[2u*TN*BN*G4N];      // layer1 gate inputs [dir][t][b][4H]
__device__ __align__(16) ULL   g_h2state[2*HN*BN];       // dup-packed h, [dir][k][b]
__device__ __align__(16) float g_pool[BN*512];           // mean_t h1 [b][2H]
__device__ unsigned g_cnt [2][8][2];
__device__ unsigned g_flag[2][8][2];

__global__ void init_kernel(){
    int i=threadIdx.x;
    if(i<32){ ((unsigned*)g_cnt)[i]=0u; ((unsigned*)g_flag)[i]=0u; }
}

// ---- scan dynamic smem layout (bytes) ----
#define SM_W    0                      // float [256][64]  wh^T slice     65536
#define SM_H2   65536                  // ULL   [256][34]  dup h (k-major) 69632
#define SM_G    (SM_H2+256*34*8)       // float [64][33]   gate staging    8448
#define SM_BS   (SM_G+64*33*4)         // float [64]
#define SM_WI0  (SM_BS+64*4)           // float [64][4]
#define SM_TOT  (SM_WI0+64*4*4)        // 144896

template<int LAYER>
__global__ void __launch_bounds__(256,1) lstm_scan_kernel(
    const float* __restrict__ x, const float* __restrict__ w_ih0,
    const float* __restrict__ w_hh, const float* __restrict__ b_ih,
    const float* __restrict__ b_hh)
{
    extern __shared__ char smem[];
    float* w_s    = (float*)(smem+SM_W);
    ULL*   h2_s   = (ULL*)  (smem+SM_H2);
    float* G_s    = (float*)(smem+SM_G);
    float* bsum_s = (float*)(smem+SM_BS);
    float* wi0_s  = (float*)(smem+SM_WI0);
    const unsigned h2_base = smem_u32(h2_s);

    const int bx=blockIdx.x, dir=bx>>6, cc=bx&63;
    const int btile=cc>>4, ntile=cc&15, tx=threadIdx.x;
    const int grp = dir*4 + btile;

    // one-time weight staging: w_s[k][jl], jl = gate*16 + nn
    for(int i=tx;i<64*256;i+=256){
        int jl=i>>8, k=i&255, gate=jl>>4, nn=jl&15;
        int row=gate*256+ntile*16+nn;
        w_s[k*64+jl]=w_hh[(dir*G4N+row)*HN+k];
    }
    for(int jl=tx;jl<64;jl+=256){
        int gate=jl>>4, nn=jl&15, row=gate*256+ntile*16+nn;
        bsum_s[jl]=b_ih[dir*G4N+row]+b_hh[dir*G4N+row];
        if(LAYER==0){
            #pragma unroll
            for(int d=0;d<4;d++) wi0_s[jl*4+d]=w_ih0[(dir*G4N+row)*4+d];
        }
    }

    // lane mapping: warp spans 4 j-groups x 8 b-groups
    const int wq=tx>>5;
    const int jgroup=(wq&3)*4 + (tx&3);
    const int bgroup=(wq>>2)*8 + ((tx>>2)&7);
    const int j0=jgroup*4, b0=bgroup*2, bglob0=btile*32;
    float c0=0.f,c1=0.f,s0=0.f,s1=0.f;

    float4 pf0, pf1, npf0, npf1;
    {
        int t0 = dir ? TN-1 : 0;
        if(LAYER==0){
            npf0 = *(const float4*)&x[((bglob0+b0  )*TN + t0)*4];
            npf1 = *(const float4*)&x[((bglob0+b0+1)*TN + t0)*4];
        } else {
            const long gb=((long)(dir*TN+t0)*BN)*G4N;
            const int col=(j0>>4)*256+ntile*16+(j0&15);
            npf0 = *(const float4*)&g_gx1[gb + (long)(bglob0+b0  )*G4N + col];
            npf1 = *(const float4*)&g_gx1[gb + (long)(bglob0+b0+1)*G4N + col];
        }
    }
    pf0=npf0; pf1=npf1;
    __syncthreads();   // weights staged

    for(int s=0;s<TN;s++){
        const int t = dir ? (TN-1-s) : s;

        cp_wait1();          // first half of h tile landed (group B may still fly)
        __syncthreads();

        // gate pre-activation base from prefetched regs
        float base[2][4];
        if(LAYER==0){
            #pragma unroll
            for(int bi=0;bi<2;bi++){
                float4 xv = bi ? pf1 : pf0;
                #pragma unroll
                for(int jj=0;jj<4;jj++){
                    int jl=j0+jj;
                    base[bi][jj]=bsum_s[jl]+wi0_s[jl*4+0]*xv.x+wi0_s[jl*4+1]*xv.y
                                           +wi0_s[jl*4+2]*xv.z+wi0_s[jl*4+3]*xv.w;
                }
            }
        } else {
            #pragma unroll
            for(int bi=0;bi<2;bi++){
                float4 gv = bi ? pf1 : pf0;
                base[bi][0]=gv.x+bsum_s[j0+0]; base[bi][1]=gv.y+bsum_s[j0+1];
                base[bi][2]=gv.z+bsum_s[j0+2]; base[bi][3]=gv.w+bsum_s[j0+3];
            }
        }
        ULL acc00=pack2(base[0][0],base[0][1]), acc01=pack2(base[0][2],base[0][3]);
        ULL acc10=pack2(base[1][0],base[1][1]), acc11=pack2(base[1][2],base[1][3]);

        // prefetch next step's gate inputs (no h dependency; overlaps GEMM)
        if(s+1<TN){
            int tn = dir ? (t-1) : (t+1);
            if(LAYER==0){
                npf0 = *(const float4*)&x[((bglob0+b0  )*TN + tn)*4];
                npf1 = *(const float4*)&x[((bglob0+b0+1)*TN + tn)*4];
            } else {
                const long gb=((long)(dir*TN+tn)*BN)*G4N;
                const int col=(j0>>4)*256+ntile*16+(j0&15);
                npf0 = *(const float4*)&g_gx1[gb + (long)(bglob0+b0  )*G4N + col];
                npf1 = *(const float4*)&g_gx1[gb + (long)(bglob0+b0+1)*G4N + col];
            }
        }

        // recurrent GEMM: g += h @ wh^T (f32x2), split at k=128 on cp group B
        if(s>0){
            const ULL* wp=(const ULL*)w_s + (j0>>1);
            const ULL* hp=h2_s + b0;
            #pragma unroll 8
            for(int k=0;k<128;k++){
                ulonglong2 hh=*(const ulonglong2*)(hp + k*34);
                ulonglong2 ww=*(const ulonglong2*)(wp + k*32);
                acc00=fma2(ww.x,hh.x,acc00); acc01=fma2(ww.y,hh.x,acc01);
                acc10=fma2(ww.x,hh.y,acc10); acc11=fma2(ww.y,hh.y,acc11);
            }
            cp_wait0(); __syncthreads();
            #pragma unroll 8
            for(int k=128;k<256;k++){
                ulonglong2 hh=*(const ulonglong2*)(hp + k*34);
                ulonglong2 ww=*(const ulonglong2*)(wp + k*32);
                acc00=fma2(ww.x,hh.x,acc00); acc01=fma2(ww.y,hh.x,acc01);
                acc10=fma2(ww.x,hh.y,acc10); acc11=fma2(ww.y,hh.y,acc11);
            }
        }

        // stage gates for the state-update transpose
        {
            float f0,f1;
            unpack2(acc00,f0,f1); G_s[(j0+0)*33+b0]  =f0; G_s[(j0+1)*33+b0]  =f1;
            unpack2(acc01,f0,f1); G_s[(j0+2)*33+b0]  =f0; G_s[(j0+3)*33+b0]  =f1;
            unpack2(acc10,f0,f1); G_s[(j0+0)*33+b0+1]=f0; G_s[(j0+1)*33+b0+1]=f1;
            unpack2(acc11,f0,f1); G_s[(j0+2)*33+b0+1]=f0; G_s[(j0+3)*33+b0+1]=f1;
        }
        __syncthreads();

        // LSTM cell update: thread owns (b0,b0+1) x n
        {
            const int nn=jgroup, n=ntile*16+nn;
            float hv[2];
            #pragma unroll
            for(int bi=0;bi<2;bi++){
                float gi=G_s[(0*16+nn)*33+b0+bi];
                float gf=G_s[(1*16+nn)*33+b0+bi];
                float gg=G_s[(2*16+nn)*33+b0+bi];
                float go=G_s[(3*16+nn)*33+b0+bi];
                float c = bi?c1:c0;
                c = sig_ap(gf)*c + sig_ap(gi)*tanh_ap(gg);
                float h = sig_ap(go)*tanh_ap(c);
                if(bi) c1=c; else c0=c;
                hv[bi]=h;
                int bg=bglob0+b0+bi;
                if(LAYER==0) g_h0[((t*BN)+bg)*512+dir*256+n]=h;
                else { if(bi) s1+=h; else s0+=h; }
            }
            ULL p0=pack2(hv[0],hv[0]), p1=pack2(hv[1],hv[1]);
            asm volatile("st.global.cg.v2.u64 [%0],{%1,%2};"
                         :: "l"(&g_h2state[(dir*HN+n)*BN + bglob0+b0]), "l"(p0), "l"(p1) : "memory");
        }
        pf0=npf0; pf1=npf1;

        if(s+1<TN){
            __syncthreads();
            if(tx==0){
                const int p=s&1; const unsigned target=(unsigned)(s+1);
                __threadfence();
                unsigned old=atomicAdd(&g_cnt[LAYER][grp][p],1u);
                if(old==15u){
                    g_cnt[LAYER][grp][p]=0u;
                    __threadfence();
                    atomicExch(&g_flag[LAYER][grp][p], target);
                } else {
                    while((int)(__ldcg(&g_flag[LAYER][grp][p]) - target) < 0) { }
                    __threadfence();
                }
            }
            __syncthreads();
            // async-copy next h tile in two groups (k<128, k>=128)
            const ULL* src_base=&g_h2state[(dir*HN)*BN + bglob0];
            for(int i=tx;i<2048;i+=256){
                int kk=i>>4, c2=(i&15)*2;
                cp16(h2_base + (unsigned)((kk*34+c2)*8), src_base + kk*BN + c2);
            }
            cp_commit();
            for(int i=tx;i<2048;i+=256){
                int kk=128+(i>>4), c2=(i&15)*2;
                cp16(h2_base + (unsigned)((kk*34+c2)*8), src_base + kk*BN + c2);
            }
            cp_commit();
        }
    }

    if(LAYER==1){
        const float inv=1.0f/(float)TN;
        const int n=ntile*16+jgroup;
        g_pool[(bglob0+b0  )*512+dir*256+n]=s0*inv;
        g_pool[(bglob0+b0+1)*512+dir*256+n]=s1*inv;
    }
}

// ---------------------------------------------------------------------------
// gx1 = h0cat @ w_ih1^T (no bias). M=65536 (t,b), N=1024/dir, K=512.
// CTA 128m x 128j, thread 8m x 8j, A dup-packed f32x2 in smem.
// ---------------------------------------------------------------------------
#define GX_A   0                    // ULL [32][130]  dup A   33280
#define GX_B   33280                // ULL [32][66]   B       16896
#define GX_SM  (GX_A+33280+16896)   // 50176

__global__ void __launch_bounds__(256,2) gx1_gemm_kernel(const float* __restrict__ w_ih1)
{
    extern __shared__ char smg[];
    ULL*   A2  = (ULL*)(smg+GX_A);
    ULL*   Bu  = (ULL*)(smg+GX_B);
    float* Bf  = (float*)Bu;

    const int dir=blockIdx.x>>3, jt=blockIdx.x&7, mt=blockIdx.y, tx=threadIdx.x;
    const int jgrp=tx&15, mgrp=tx>>4;
    const int j0=jgrp*8, m0=mgrp*8;
    const int mbase=mt*128, jbase=jt*128;

    ULL acc[8][4];
    #pragma unroll
    for(int i=0;i<8;i++)
        #pragma unroll
        for(int j=0;j<4;j++) acc[i][j]=0ull;

    for(int kc=0;kc<512;kc+=32){
        for(int i=tx;i<4096;i+=256){                  // A: 128m x 32k, dup-pack
            int mm=i>>5, kk=i&31;
            float v=g_h0[(mbase+mm)*512+kc+kk];
            A2[kk*130+mm]=pack2(v,v);
        }
        for(int i=tx;i<4096;i+=256){                  // B: 128j x 32k
            int jj=i>>5, kk=i&31;
            Bf[kk*132+jj]=w_ih1[((dir*G4N)+jbase+jj)*512+kc+kk];
        }
        __syncthreads();
        const ULL* ap=A2+m0;
        const ULL* bp=Bu+(j0>>1);
        #pragma unroll 8
        for(int k=0;k<32;k++){
            ulonglong2 a01=*(const ulonglong2*)(ap+k*130);
            ulonglong2 a23=*(const ulonglong2*)(ap+k*130+2);
            ulonglong2 a45=*(const ulonglong2*)(ap+k*130+4);
            ulonglong2 a67=*(const ulonglong2*)(ap+k*130+6);
            ulonglong2 b01=*(const ulonglong2*)(bp+k*66);
            ulonglong2 b23=*(const ulonglong2*)(bp+k*66+2);
            acc[0][0]=fma2(b01.x,a01.x,acc[0][0]); acc[0][1]=fma2(b01.y,a01.x,acc[0][1]);
            acc[0][2]=fma2(b23.x,a01.x,acc[0][2]); acc[0][3]=fma2(b23.y,a01.x,acc[0][3]);
            acc[1][0]=fma2(b01.x,a01.y,acc[1][0]); acc[1][1]=fma2(b01.y,a01.y,acc[1][1]);
            acc[1][2]=fma2(b23.x,a01.y,acc[1][2]); acc[1][3]=fma2(b23.y,a01.y,acc[1][3]);
            acc[2][0]=fma2(b01.x,a23.x,acc[2][0]); acc[2][1]=fma2(b01.y,a23.x,acc[2][1]);
            acc[2][2]=fma2(b23.x,a23.x,acc[2][2]); acc[2][3]=fma2(b23.y,a23.x,acc[2][3]);
            acc[3][0]=fma2(b01.x,a23.y,acc[3][0]); acc[3][1]=fma2(b01.y,a23.y,acc[3][1]);
            acc[3][2]=fma2(b23.x,a23.y,acc[3][2]); acc[3][3]=fma2(b23.y,a23.y,acc[3][3]);
            acc[4][0]=fma2(b01.x,a45.x,acc[4][0]); acc[4][1]=fma2(b01.y,a45.x,acc[4][1]);
            acc[4][2]=fma2(b23.x,a45.x,acc[4][2]); acc[4][3]=fma2(b23.y,a45.x,acc[4][3]);
            acc[5][0]=fma2(b01.x,a45.y,acc[5][0]); acc[5][1]=fma2(b01.y,a45.y,acc[5][1]);
            acc[5][2]=fma2(b23.x,a45.y,acc[5][2]); acc[5][3]=fma2(b23.y,a45.y,acc[5][3]);
            acc[6][0]=fma2(b01.x,a67.x,acc[6][0]); acc[6][1]=fma2(b01.y,a67.x,acc[6][1]);
            acc[6][2]=fma2(b23.x,a67.x,acc[6][2]); acc[6][3]=fma2(b23.y,a67.x,acc[6][3]);
            acc[7][0]=fma2(b01.x,a67.y,acc[7][0]); acc[7][1]=fma2(b01.y,a67.y,acc[7][1]);
            acc[7][2]=fma2(b23.x,a67.y,acc[7][2]); acc[7][3]=fma2(b23.y,a67.y,acc[7][3]);
        }
        __syncthreads();
    }

    #pragma unroll
    for(int i=0;i<8;i++){
        int m=mbase+m0+i, t=m>>7, b=m&127;
        float* dst=&g_gx1[(((long)dir*TN+t)*BN+b)*G4N+jbase+j0];
        float l0,h0_,l1,h1_;
        unpack2(acc[i][0],l0,h0_); unpack2(acc[i][1],l1,h1_);
        *(float4*)dst = make_float4(l0,h0_,l1,h1_);
        unpack2(acc[i][2],l0,h0_); unpack2(acc[i][3],l1,h1_);
        *(float4*)(dst+4) = make_float4(l0,h0_,l1,h1_);
    }
}

__global__ void fc_kernel(const float* __restrict__ fc_w, const float* __restrict__ fc_b,
                          float* __restrict__ out)
{
    int b=blockIdx.x;
    int o=threadIdx.x>>5, lane=threadIdx.x&31;
    const float* p=&g_pool[b*512];
    const float* w=&fc_w[o*512];
    float s=0.f;
    #pragma unroll 4
    for(int k=lane;k<512;k+=32) s+=p[k]*w[k];
    #pragma unroll
    for(int off=16;off;off>>=1) s+=__shfl_xor_sync(0xffffffffu,s,off);
    if(lane==0) out[b*2+o]=s+fc_b[o];
}

extern "C" void kernel_launch(void* const* d_in, const int* in_sizes, int n_in,
                              void* d_out, int out_size)
{
    const float* x     =(const float*)d_in[0];
    const float* w_ih0 =(const float*)d_in[1];
    const float* w_hh0 =(const float*)d_in[2];
    const float* b_ih0 =(const float*)d_in[3];
    const float* b_hh0 =(const float*)d_in[4];
    const float* w_ih1 =(const float*)d_in[5];
    const float* w_hh1 =(const float*)d_in[6];
    const float* b_ih1 =(const float*)d_in[7];
    const float* b_hh1 =(const float*)d_in[8];
    const float* fc_w  =(const float*)d_in[9];
    const float* fc_b  =(const float*)d_in[10];
    float* out=(float*)d_out;

    cudaFuncSetAttribute(lstm_scan_kernel<0>, cudaFuncAttributeMaxDynamicSharedMemorySize, SM_TOT);
    cudaFuncSetAttribute(lstm_scan_kernel<1>, cudaFuncAttributeMaxDynamicSharedMemorySize, SM_TOT);
    cudaFuncSetAttribute(gx1_gemm_kernel,     cudaFuncAttributeMaxDynamicSharedMemorySize, GX_SM);

    init_kernel<<<1,32>>>();
    lstm_scan_kernel<0><<<128,256,SM_TOT>>>(x, w_ih0, w_hh0, b_ih0, b_hh0);
    gx1_gemm_kernel<<<dim3(16,512),256,GX_SM>>>(w_ih1);
    lstm_scan_kernel<1><<<128,256,SM_TOT>>>(nullptr, nullptr, w_hh1, b_ih1, b_hh1);
    fc_kernel<<<128,64>>>(fc_w, fc_b, out);
}

// round 16
// speedup vs baseline: 1.3567x; 1.0291x over previous
#include <cuda_runtime.h>

#define BN 128
#define TN 512
#define HN 256
#define G4N 1024
typedef unsigned long long ULL;

__device__ __forceinline__ ULL pack2(float x, float y){ULL r;asm("mov.b64 %0,{%1,%2};":"=l"(r):"f"(x),"f"(y));return r;}
__device__ __forceinline__ void unpack2(ULL v,float&x,float&y){asm("mov.b64 {%0,%1},%2;":"=f"(x),"=f"(y):"l"(v));}
__device__ __forceinline__ ULL fma2(ULL a,ULL b,ULL c){ULL d;asm("fma.rn.f32x2 %0,%1,%2,%3;":"=l"(d):"l"(a),"l"(b),"l"(c));return d;}
__device__ __forceinline__ unsigned smem_u32(const void* p){ return (unsigned)__cvta_generic_to_shared(p); }
__device__ __forceinline__ void cp16(unsigned dst, const void* src){
    asm volatile("cp.async.cg.shared.global [%0], [%1], 16;\n" :: "r"(dst), "l"(src) : "memory");
}
__device__ __forceinline__ void cp_commit(){ asm volatile("cp.async.commit_group;\n":::"memory"); }
__device__ __forceinline__ void cp_wait0(){ asm volatile("cp.async.wait_group 0;\n":::"memory"); }
__device__ __forceinline__ void cp_wait1(){ asm volatile("cp.async.wait_group 1;\n":::"memory"); }

// accurate-enough activations: ex2/rcp MUFU (rel err ~1e-6, vs 6e-4 for tanh.approx)
__device__ __forceinline__ float ex2_ap(float x){float y;asm("ex2.approx.f32 %0,%1;":"=f"(y):"f"(x));return y;}
__device__ __forceinline__ float rcp_ap(float x){float y;asm("rcp.approx.f32 %0,%1;":"=f"(y):"f"(x));return y;}
__device__ __forceinline__ float sig_f(float x){ return rcp_ap(1.0f + ex2_ap(-1.4426950408889634f*x)); }
__device__ __forceinline__ float tanh_f(float x){ return fmaf(2.0f, rcp_ap(1.0f + ex2_ap(-2.8853900817779268f*x)), -1.0f); }

// ---- scratch (static __device__) ----
__device__ __align__(16) float g_h0[TN*BN*512];          // layer0 out [t][b][2H]
__device__ __align__(16) float g_gx1[2u*TN*BN*G4N];      // layer1 gate inputs [dir][t][b][n*4+gate]
__device__ __align__(16) float g_hf[2*HN*BN];            // h state, [dir][n][b]
__device__ __align__(16) float g_pool[BN*512];           // mean_t h1 [b][2H]
__device__ unsigned g_cnt [2][8][2];
__device__ unsigned g_flag[2][8][2];

__global__ void init_kernel(){
    int i=threadIdx.x;
    if(i<32){ ((unsigned*)g_cnt)[i]=0u; ((unsigned*)g_flag)[i]=0u; }
}

// ---- scan dynamic smem (bytes) ----
#define SM_W    0                        // ULL  [256][64]  dup wh^T (gate-major)  131072
#define SM_H    131072                   // float[256][32]  h tile (k-major)        32768
#define SM_BS   (SM_H+32768)             // float [64]      bias (gate-major)         256
#define SM_WI0  (SM_BS+256)              // float [64][4]                            1024
#define SM_TOT  (SM_WI0+1024)            // 165120

template<int LAYER>
__global__ void __launch_bounds__(256,1) lstm_scan_kernel(
    const float* __restrict__ x, const float* __restrict__ w_ih0,
    const float* __restrict__ w_hh, const float* __restrict__ b_ih,
    const float* __restrict__ b_hh)
{
    extern __shared__ char smem[];
    ULL*   w2_s   = (ULL*)  (smem+SM_W);
    float* h_s    = (float*)(smem+SM_H);
    float* bsum_s = (float*)(smem+SM_BS);
    float* wi0_s  = (float*)(smem+SM_WI0);
    const unsigned h_base = smem_u32(h_s);

    const int bx=blockIdx.x, dir=bx>>6, cc=bx&63;
    const int btile=cc>>4, ntile=cc&15, tx=threadIdx.x;
    const int grp = dir*4 + btile;

    // one-time staging: w2_s[k][nn*4+gate] = dup(w_hh[gate*256+ntile*16+nn][k])
    for(int i=tx;i<64*256;i+=256){
        int jl=i>>8, k=i&255, nn=jl>>2, gate=jl&3;
        int row=gate*256+ntile*16+nn;
        float v=w_hh[(dir*G4N+row)*HN+k];
        w2_s[k*64+jl]=pack2(v,v);
    }
    for(int jl=tx;jl<64;jl+=256){
        int nn=jl>>2, gate=jl&3, row=gate*256+ntile*16+nn;
        bsum_s[jl]=b_ih[dir*G4N+row]+b_hh[dir*G4N+row];
        if(LAYER==0){
            #pragma unroll
            for(int d=0;d<4;d++) wi0_s[jl*4+d]=w_ih0[(dir*G4N+row)*4+d];
        }
    }

    // thread mapping: nn = tx>>4 (hidden unit), bp = tx&15 (batch pair)
    const int nn=tx>>4, bp=tx&15;
    const int n=ntile*16+nn, b0=bp*2, bglob0=btile*32;
    float c0=0.f,c1=0.f,s0=0.f,s1=0.f;

    float4 pf0, pf1, npf0, npf1;
    {
        int t0 = dir ? TN-1 : 0;
        if(LAYER==0){
            npf0 = *(const float4*)&x[((bglob0+b0  )*TN + t0)*4];
            npf1 = *(const float4*)&x[((bglob0+b0+1)*TN + t0)*4];
        } else {
            const long gb=((long)(dir*TN+t0)*BN)*G4N;
            npf0 = *(const float4*)&g_gx1[gb + (long)(bglob0+b0  )*G4N + n*4];
            npf1 = *(const float4*)&g_gx1[gb + (long)(bglob0+b0+1)*G4N + n*4];
        }
    }
    pf0=npf0; pf1=npf1;
    __syncthreads();   // staging done

    for(int s=0;s<TN;s++){
        const int t = dir ? (TN-1-s) : s;

        // gate pre-activation bases (gate-major): base[gate] packs (b0,b0+1)
        float ba0[4], ba1[4];
        if(LAYER==0){
            #pragma unroll
            for(int g=0;g<4;g++){
                int jl=nn*4+g;
                ba0[g]=bsum_s[jl]+wi0_s[jl*4+0]*pf0.x+wi0_s[jl*4+1]*pf0.y
                                 +wi0_s[jl*4+2]*pf0.z+wi0_s[jl*4+3]*pf0.w;
                ba1[g]=bsum_s[jl]+wi0_s[jl*4+0]*pf1.x+wi0_s[jl*4+1]*pf1.y
                                 +wi0_s[jl*4+2]*pf1.z+wi0_s[jl*4+3]*pf1.w;
            }
        } else {
            ba0[0]=pf0.x+bsum_s[nn*4+0]; ba0[1]=pf0.y+bsum_s[nn*4+1];
            ba0[2]=pf0.z+bsum_s[nn*4+2]; ba0[3]=pf0.w+bsum_s[nn*4+3];
            ba1[0]=pf1.x+bsum_s[nn*4+0]; ba1[1]=pf1.y+bsum_s[nn*4+1];
            ba1[2]=pf1.z+bsum_s[nn*4+2]; ba1[3]=pf1.w+bsum_s[nn*4+3];
        }
        ULL acc0=pack2(ba0[0],ba1[0]), acc1=pack2(ba0[1],ba1[1]);
        ULL acc2=pack2(ba0[2],ba1[2]), acc3=pack2(ba0[3],ba1[3]);

        // prefetch next step's gate inputs (no h dependency)
        if(s+1<TN){
            int tn = dir ? (t-1) : (t+1);
            if(LAYER==0){
                npf0 = *(const float4*)&x[((bglob0+b0  )*TN + tn)*4];
                npf1 = *(const float4*)&x[((bglob0+b0+1)*TN + tn)*4];
            } else {
                const long gb=((long)(dir*TN+tn)*BN)*G4N;
                npf0 = *(const float4*)&g_gx1[gb + (long)(bglob0+b0  )*G4N + n*4];
                npf1 = *(const float4*)&g_gx1[gb + (long)(bglob0+b0+1)*G4N + n*4];
            }
        }

        // recurrent GEMM: acc_g += w2[k][nn*4+g] * (h[k][b0],h[k][b0+1])
        if(s>0){
            cp_wait1();  __syncthreads();      // first half of h tile landed
            const ULL* wp=w2_s + nn*4;
            const float* hp=h_s + b0;
            #pragma unroll 8
            for(int k=0;k<128;k++){
                ULL h2=*(const ULL*)(hp + k*32);
                ulonglong2 w01=*(const ulonglong2*)(wp + k*64);
                ulonglong2 w23=*(const ulonglong2*)(wp + k*64 + 2);
                acc0=fma2(w01.x,h2,acc0); acc1=fma2(w01.y,h2,acc1);
                acc2=fma2(w23.x,h2,acc2); acc3=fma2(w23.y,h2,acc3);
            }
            cp_wait0(); __syncthreads();
            #pragma unroll 8
            for(int k=128;k<256;k++){
                ULL h2=*(const ULL*)(hp + k*32);
                ulonglong2 w01=*(const ulonglong2*)(wp + k*64);
                ulonglong2 w23=*(const ulonglong2*)(wp + k*64 + 2);
                acc0=fma2(w01.x,h2,acc0); acc1=fma2(w01.y,h2,acc1);
                acc2=fma2(w23.x,h2,acc2); acc3=fma2(w23.y,h2,acc3);
            }
        }

        // cell update entirely in registers (gate-major accs)
        {
            float gi0,gi1,gf0,gf1,gg0,gg1,go0,go1;
            unpack2(acc0,gi0,gi1); unpack2(acc1,gf0,gf1);
            unpack2(acc2,gg0,gg1); unpack2(acc3,go0,go1);
            c0 = sig_f(gf0)*c0 + sig_f(gi0)*tanh_f(gg0);
            c1 = sig_f(gf1)*c1 + sig_f(gi1)*tanh_f(gg1);
            float h0v = sig_f(go0)*tanh_f(c0);
            float h1v = sig_f(go1)*tanh_f(c1);
            ULL hp2=pack2(h0v,h1v);
            asm volatile("st.global.cg.u64 [%0],%1;"
                         :: "l"(&g_hf[(dir*HN+n)*BN + bglob0+b0]), "l"(hp2) : "memory");
            if(LAYER==0){
                g_h0[((t*BN)+bglob0+b0  )*512+dir*256+n]=h0v;
                g_h0[((t*BN)+bglob0+b0+1)*512+dir*256+n]=h1v;
            } else { s0+=h0v; s1+=h1v; }
        }
        pf0=npf0; pf1=npf1;

        if(s+1<TN){
            __syncthreads();
            if(tx==0){
                const int p=s&1; const unsigned target=(unsigned)(s+1);
                __threadfence();
                unsigned old=atomicAdd(&g_cnt[LAYER][grp][p],1u);
                if(old==15u){
                    g_cnt[LAYER][grp][p]=0u;
                    __threadfence();
                    atomicExch(&g_flag[LAYER][grp][p], target);
                } else {
                    while((int)(__ldcg(&g_flag[LAYER][grp][p]) - target) < 0) { }
                    __threadfence();
                }
            }
            __syncthreads();
            // async-copy next h tile (32KB), two groups (k<128 | k>=128)
            const float* src=&g_hf[(dir*HN)*BN + bglob0];
            for(int i=tx;i<1024;i+=256){
                int kk=i>>3, c4=(i&7)*4;
                cp16(h_base + (unsigned)((kk*32+c4)*4), src + kk*BN + c4);
            }
            cp_commit();
            for(int i=tx;i<1024;i+=256){
                int kk=128+(i>>3), c4=(i&7)*4;
                cp16(h_base + (unsigned)((kk*32+c4)*4), src + kk*BN + c4);
            }
            cp_commit();
        }
    }

    if(LAYER==1){
        const float inv=1.0f/(float)TN;
        g_pool[(bglob0+b0  )*512+dir*256+n]=s0*inv;
        g_pool[(bglob0+b0+1)*512+dir*256+n]=s1*inv;
    }
}

// ---------------------------------------------------------------------------
// gx1 = h0cat @ w_ih1^T, output columns permuted to n*4+gate.
// M=65536, N'=1024/dir, K=512. CTA 128m x 128j, thread 8m x 8j, f32x2.
// ---------------------------------------------------------------------------
#define GX_A   0                    // ULL [32][130]  dup A   33280
#define GX_B   33280                // float [32][132] B      16896
#define GX_SM  (GX_A+33280+16896)

__global__ void __launch_bounds__(256,2) gx1_gemm_kernel(const float* __restrict__ w_ih1)
{
    extern __shared__ char smg[];
    ULL*   A2  = (ULL*)(smg+GX_A);
    ULL*   Bu  = (ULL*)(smg+GX_B);
    float* Bf  = (float*)Bu;

    const int dir=blockIdx.x>>3, jt=blockIdx.x&7, mt=blockIdx.y, tx=threadIdx.x;
    const int jgrp=tx&15, mgrp=tx>>4;
    const int j0=jgrp*8, m0=mgrp*8;
    const int mbase=mt*128, jbase=jt*128;

    ULL acc[8][4];
    #pragma unroll
    for(int i=0;i<8;i++)
        #pragma unroll
        for(int j=0;j<4;j++) acc[i][j]=0ull;

    for(int kc=0;kc<512;kc+=32){
        for(int i=tx;i<4096;i+=256){                  // A: 128m x 32k, dup-pack
            int mm=i>>5, kk=i&31;
            float v=g_h0[(mbase+mm)*512+kc+kk];
            A2[kk*130+mm]=pack2(v,v);
        }
        for(int i=tx;i<4096;i+=256){                  // B: permuted rows N'=n*4+g
            int jj=i>>5, kk=i&31;
            int np=jbase+jj, row=(np&3)*256+(np>>2);
            Bf[kk*132+jj]=w_ih1[((dir*G4N)+row)*512+kc+kk];
        }
        __syncthreads();
        const ULL* ap=A2+m0;
        const ULL* bp=Bu+(j0>>1);
        #pragma unroll 8
        for(int k=0;k<32;k++){
            ulonglong2 a01=*(const ulonglong2*)(ap+k*130);
            ulonglong2 a23=*(const ulonglong2*)(ap+k*130+2);
            ulonglong2 a45=*(const ulonglong2*)(ap+k*130+4);
            ulonglong2 a67=*(const ulonglong2*)(ap+k*130+6);
            ulonglong2 b01=*(const ulonglong2*)(bp+k*66);
            ulonglong2 b23=*(const ulonglong2*)(bp+k*66+2);
            acc[0][0]=fma2(b01.x,a01.x,acc[0][0]); acc[0][1]=fma2(b01.y,a01.x,acc[0][1]);
            acc[0][2]=fma2(b23.x,a01.x,acc[0][2]); acc[0][3]=fma2(b23.y,a01.x,acc[0][3]);
            acc[1][0]=fma2(b01.x,a01.y,acc[1][0]); acc[1][1]=fma2(b01.y,a01.y,acc[1][1]);
            acc[1][2]=fma2(b23.x,a01.y,acc[1][2]); acc[1][3]=fma2(b23.y,a01.y,acc[1][3]);
            acc[2][0]=fma2(b01.x,a23.x,acc[2][0]); acc[2][1]=fma2(b01.y,a23.x,acc[2][1]);
            acc[2][2]=fma2(b23.x,a23.x,acc[2][2]); acc[2][3]=fma2(b23.y,a23.x,acc[2][3]);
            acc[3][0]=fma2(b01.x,a23.y,acc[3][0]); acc[3][1]=fma2(b01.y,a23.y,acc[3][1]);
            acc[3][2]=fma2(b23.x,a23.y,acc[3][2]); acc[3][3]=fma2(b23.y,a23.y,acc[3][3]);
            acc[4][0]=fma2(b01.x,a45.x,acc[4][0]); acc[4][1]=fma2(b01.y,a45.x,acc[4][1]);
            acc[4][2]=fma2(b23.x,a45.x,acc[4][2]); acc[4][3]=fma2(b23.y,a45.x,acc[4][3]);
            acc[5][0]=fma2(b01.x,a45.y,acc[5][0]); acc[5][1]=fma2(b01.y,a45.y,acc[5][1]);
            acc[5][2]=fma2(b23.x,a45.y,acc[5][2]); acc[5][3]=fma2(b23.y,a45.y,acc[5][3]);
            acc[6][0]=fma2(b01.x,a67.x,acc[6][0]); acc[6][1]=fma2(b01.y,a67.x,acc[6][1]);
            acc[6][2]=fma2(b23.x,a67.x,acc[6][2]); acc[6][3]=fma2(b23.y,a67.x,acc[6][3]);
            acc[7][0]=fma2(b01.x,a67.y,acc[7][0]); acc[7][1]=fma2(b01.y,a67.y,acc[7][1]);
            acc[7][2]=fma2(b23.x,a67.y,acc[7][2]); acc[7][3]=fma2(b23.y,a67.y,acc[7][3]);
        }
        __syncthreads();
    }

    #pragma unroll
    for(int i=0;i<8;i++){
        int m=mbase+m0+i, t=m>>7, b=m&127;
        float* dst=&g_gx1[(((long)dir*TN+t)*BN+b)*G4N+jbase+j0];
        float l0,h0_,l1,h1_;
        unpack2(acc[i][0],l0,h0_); unpack2(acc[i][1],l1,h1_);
        *(float4*)dst = make_float4(l0,h0_,l1,h1_);
        unpack2(acc[i][2],l0,h0_); unpack2(acc[i][3],l1,h1_);
        *(float4*)(dst+4) = make_float4(l0,h0_,l1,h1_);
    }
}

__global__ void fc_kernel(const float* __restrict__ fc_w, const float* __restrict__ fc_b,
                          float* __restrict__ out)
{
    int b=blockIdx.x;
    int o=threadIdx.x>>5, lane=threadIdx.x&31;
    const float* p=&g_pool[b*512];
    const float* w=&fc_w[o*512];
    float s=0.f;
    #pragma unroll 4
    for(int k=lane;k<512;k+=32) s+=p[k]*w[k];
    #pragma unroll
    for(int off=16;off;off>>=1) s+=__shfl_xor_sync(0xffffffffu,s,off);
    if(lane==0) out[b*2+o]=s+fc_b[o];
}

extern "C" void kernel_launch(void* const* d_in, const int* in_sizes, int n_in,
                              void* d_out, int out_size)
{
    const float* x     =(const float*)d_in[0];
    const float* w_ih0 =(const float*)d_in[1];
    const float* w_hh0 =(const float*)d_in[2];
    const float* b_ih0 =(const float*)d_in[3];
    const float* b_hh0 =(const float*)d_in[4];
    const float* w_ih1 =(const float*)d_in[5];
    const float* w_hh1 =(const float*)d_in[6];
    const float* b_ih1 =(const float*)d_in[7];
    const float* b_hh1 =(const float*)d_in[8];
    const float* fc_w  =(const float*)d_in[9];
    const float* fc_b  =(const float*)d_in[10];
    float* out=(float*)d_out;

    cudaFuncSetAttribute(lstm_scan_kernel<0>, cudaFuncAttributeMaxDynamicSharedMemorySize, SM_TOT);
    cudaFuncSetAttribute(lstm_scan_kernel<1>, cudaFuncAttributeMaxDynamicSharedMemorySize, SM_TOT);
    cudaFuncSetAttribute(gx1_gemm_kernel,     cudaFuncAttributeMaxDynamicSharedMemorySize, GX_SM);

    init_kernel<<<1,32>>>();
    lstm_scan_kernel<0><<<128,256,SM_TOT>>>(x, w_ih0, w_hh0, b_ih0, b_hh0);
    gx1_gemm_kernel<<<dim3(16,512),256,GX_SM>>>(w_ih1);
    lstm_scan_kernel<1><<<128,256,SM_TOT>>>(nullptr, nullptr, w_hh1, b_ih1, b_hh1);
    fc_kernel<<<128,64>>>(fc_w, fc_b, out);
}